// round 6
// baseline (speedup 1.0000x reference)
#include <cuda_runtime.h>

#define NN 100000
#define NE 1000000
#define DI 128
#define DO 64
#define SB 1024
#define NBLK_SCAN ((NN + SB - 1) / SB)   // 98
#define NSUMB 256

// ---------------- scratch (device globals) ----------------------------------
__device__ float g_h0[NN * DO];
__device__ float g_h [NN * DO];
__device__ float g_A [NN * DO];
__device__ int   g_degd[NN];
__device__ int   g_degs[NN];
__device__ int   g_offd[NN + 1];
__device__ int   g_offs[NN + 1];
__device__ int   g_curd[NN];
__device__ int   g_curs[NN];
__device__ int   g_csrd[NE];
__device__ int   g_csrs[NE];
__device__ int   g_flag[NBLK_SCAN];
__device__ int   g_aggd[NBLK_SCAN];
__device__ int   g_aggs[NBLK_SCAN];
__device__ int   g_prefd[NBLK_SCAN];
__device__ int   g_prefs[NBLK_SCAN];
__device__ float g_e[NN];
__device__ float g_nh[NN];
__device__ float g_q[NN];
__device__ float g_dinv[NN];
__device__ float g_pm[NSUMB];
__device__ float g_pz[NSUMB];
__device__ float g_pt[NSUMB];

// ---------------- CSR build --------------------------------------------------
__global__ __launch_bounds__(256) void k_zero() {
    int i = blockIdx.x * 256 + threadIdx.x;
    if (i < NN) { g_degd[i] = 0; g_degs[i] = 0; }
    if (i < NBLK_SCAN) g_flag[i] = 0;
}

__global__ __launch_bounds__(256) void k_deg(const int* __restrict__ ei) {
    int e = blockIdx.x * 256 + threadIdx.x;
    if (e >= NE) return;
    atomicAdd(&g_degs[ei[e]], 1);
    atomicAdd(&g_degd[ei[NE + e]], 1);
}

// single-pass scan with decoupled lookback; also writes cur & dinv
__global__ __launch_bounds__(SB) void k_scan() {
    __shared__ int sd[SB], ss[SB];
    __shared__ int s_exd, s_exs;
    int t = threadIdx.x, blk = blockIdx.x;
    int i = blk * SB + t;
    int a = (i < NN) ? g_degd[i] : 0;
    int b = (i < NN) ? g_degs[i] : 0;
    sd[t] = a; ss[t] = b;
    __syncthreads();
    for (int o = 1; o < SB; o <<= 1) {
        int va = (t >= o) ? sd[t - o] : 0;
        int vb = (t >= o) ? ss[t - o] : 0;
        __syncthreads();
        sd[t] += va; ss[t] += vb;
        __syncthreads();
    }
    if (t == 0) {
        int Ad = sd[SB - 1], As = ss[SB - 1];
        if (blk == 0) {
            g_prefd[0] = Ad; g_prefs[0] = As;
            __threadfence();
            g_flag[0] = 2;
            s_exd = 0; s_exs = 0;
        } else {
            g_aggd[blk] = Ad; g_aggs[blk] = As;
            __threadfence();
            g_flag[blk] = 1;
            int exd = 0, exs = 0;
            int j = blk - 1;
            while (true) {
                int f;
                while ((f = ((volatile int*)g_flag)[j]) == 0) {}
                __threadfence();
                if (f == 2) {
                    exd += ((volatile int*)g_prefd)[j];
                    exs += ((volatile int*)g_prefs)[j];
                    break;
                }
                exd += ((volatile int*)g_aggd)[j];
                exs += ((volatile int*)g_aggs)[j];
                j--;
            }
            g_prefd[blk] = exd + Ad; g_prefs[blk] = exs + As;
            __threadfence();
            g_flag[blk] = 2;
            s_exd = exd; s_exs = exs;
        }
    }
    __syncthreads();
    if (i < NN) {
        int od = s_exd + sd[t] - a;
        int os = s_exs + ss[t] - b;
        g_offd[i] = od; g_curd[i] = od;
        g_offs[i] = os; g_curs[i] = os;
        g_dinv[i] = rsqrtf((float)(a + 1));
    }
    if (i == 0) { g_offd[NN] = NE; g_offs[NN] = NE; }
}

__global__ __launch_bounds__(256) void k_fill_d(const int* __restrict__ ei) {
    int e = blockIdx.x * 256 + threadIdx.x;
    if (e >= NE) return;
    int s = ei[e], d = ei[NE + e];
    int pd = atomicAdd(&g_curd[d], 1);
    g_csrd[pd] = s;
}

__global__ __launch_bounds__(256) void k_fill_s(const int* __restrict__ ei) {
    int e = blockIdx.x * 256 + threadIdx.x;
    if (e >= NE) return;
    int s = ei[e], d = ei[NE + e];
    int ps = atomicAdd(&g_curs[s], 1);
    g_csrs[ps] = d;
}

// ---------------- GEMM: h0 = x @ W (128 rows/block, 8x8 per thread) ----------
__global__ __launch_bounds__(128) void k_gemm(const float* __restrict__ x,
                                              const float* __restrict__ W) {
    __shared__ float Ws[DI * DO];
    __shared__ float xs[16 * 128];
    int t = threadIdx.x;
    int row0 = blockIdx.x * 128;
    for (int i = t * 4; i < DI * DO; i += 128 * 4)
        *(float4*)(Ws + i) = *(const float4*)(W + i);

    int cg = t & 7, rt = t >> 3;
    float acc[8][8];
#pragma unroll
    for (int i = 0; i < 8; i++)
#pragma unroll
        for (int j = 0; j < 8; j++) acc[i][j] = 0.f;

    int grow = row0 + t;
    bool rok = grow < NN;

    for (int kc = 0; kc < 8; kc++) {
        __syncthreads();
        float4 xa = rok ? *(const float4*)(x + grow * DI + kc * 16 + 0)  : make_float4(0,0,0,0);
        float4 xb = rok ? *(const float4*)(x + grow * DI + kc * 16 + 4)  : make_float4(0,0,0,0);
        float4 xc = rok ? *(const float4*)(x + grow * DI + kc * 16 + 8)  : make_float4(0,0,0,0);
        float4 xd = rok ? *(const float4*)(x + grow * DI + kc * 16 + 12) : make_float4(0,0,0,0);
        xs[0*128+t]=xa.x;  xs[1*128+t]=xa.y;  xs[2*128+t]=xa.z;  xs[3*128+t]=xa.w;
        xs[4*128+t]=xb.x;  xs[5*128+t]=xb.y;  xs[6*128+t]=xb.z;  xs[7*128+t]=xb.w;
        xs[8*128+t]=xc.x;  xs[9*128+t]=xc.y;  xs[10*128+t]=xc.z; xs[11*128+t]=xc.w;
        xs[12*128+t]=xd.x; xs[13*128+t]=xd.y; xs[14*128+t]=xd.z; xs[15*128+t]=xd.w;
        __syncthreads();
#pragma unroll
        for (int k = 0; k < 16; k++) {
            float4 x0 = *(const float4*)(xs + k * 128 + rt * 8);
            float4 x1 = *(const float4*)(xs + k * 128 + rt * 8 + 4);
            float4 w0 = *(const float4*)(Ws + (kc * 16 + k) * DO + cg * 8);
            float4 w1 = *(const float4*)(Ws + (kc * 16 + k) * DO + cg * 8 + 4);
            float xv[8] = {x0.x, x0.y, x0.z, x0.w, x1.x, x1.y, x1.z, x1.w};
            float wv[8] = {w0.x, w0.y, w0.z, w0.w, w1.x, w1.y, w1.z, w1.w};
#pragma unroll
            for (int i = 0; i < 8; i++)
#pragma unroll
                for (int j = 0; j < 8; j++)
                    acc[i][j] += xv[i] * wv[j];
        }
    }
#pragma unroll
    for (int i = 0; i < 8; i++) {
        int gr = row0 + rt * 8 + i;
        if (gr < NN) {
            float4* p = (float4*)(g_h0 + gr * DO + cg * 8);
            p[0] = make_float4(acc[i][0], acc[i][1], acc[i][2], acc[i][3]);
            p[1] = make_float4(acc[i][4], acc[i][5], acc[i][6], acc[i][7]);
        }
    }
}

// ---------------- gather passes (8 lanes per node, 2 float4 per lane) ---------
__global__ __launch_bounds__(256) void k_pass1(const float* __restrict__ b) {
    int t = blockIdx.x * 256 + threadIdx.x;
    int v = t >> 3, q = t & 7;
    if (v >= NN) return;
    int start = g_offd[v], end = g_offd[v + 1];
    float4 A0 = make_float4(0,0,0,0), A1 = make_float4(0,0,0,0);
    int i = start;
    for (; i + 1 < end; i += 2) {
        int i0 = g_csrd[i], i1 = g_csrd[i + 1];
        float d0 = g_dinv[i0], d1 = g_dinv[i1];
        const float4* p0 = (const float4*)(g_h0 + i0 * DO + q * 8);
        const float4* p1 = (const float4*)(g_h0 + i1 * DO + q * 8);
        float4 u0 = p0[0], u1 = p0[1];
        float4 w0 = p1[0], w1 = p1[1];
        A0.x += u0.x * d0 + w0.x * d1; A0.y += u0.y * d0 + w0.y * d1;
        A0.z += u0.z * d0 + w0.z * d1; A0.w += u0.w * d0 + w0.w * d1;
        A1.x += u1.x * d0 + w1.x * d1; A1.y += u1.y * d0 + w1.y * d1;
        A1.z += u1.z * d0 + w1.z * d1; A1.w += u1.w * d0 + w1.w * d1;
    }
    if (i < end) {
        int i0 = g_csrd[i];
        float d0 = g_dinv[i0];
        const float4* p0 = (const float4*)(g_h0 + i0 * DO + q * 8);
        float4 u0 = p0[0], u1 = p0[1];
        A0.x += u0.x * d0; A0.y += u0.y * d0; A0.z += u0.z * d0; A0.w += u0.w * d0;
        A1.x += u1.x * d0; A1.y += u1.y * d0; A1.z += u1.z * d0; A1.w += u1.w * d0;
    }
    float dv = g_dinv[v];
    float dv2 = dv * dv;
    const float4* h0p = (const float4*)(g_h0 + v * DO + q * 8);
    float4 h0a = h0p[0], h0b = h0p[1];
    const float4* bp = (const float4*)(b + q * 8);
    float4 ba = bp[0], bb = bp[1];
    float4 ha, hb;
    ha.x = dv * A0.x + dv2 * h0a.x + ba.x;
    ha.y = dv * A0.y + dv2 * h0a.y + ba.y;
    ha.z = dv * A0.z + dv2 * h0a.z + ba.z;
    ha.w = dv * A0.w + dv2 * h0a.w + ba.w;
    hb.x = dv * A1.x + dv2 * h0b.x + bb.x;
    hb.y = dv * A1.y + dv2 * h0b.y + bb.y;
    hb.z = dv * A1.z + dv2 * h0b.z + bb.z;
    hb.w = dv * A1.w + dv2 * h0b.w + bb.w;
    float4* hp = (float4*)(g_h + v * DO + q * 8);
    hp[0] = ha; hp[1] = hb;
    float p = ha.x * ha.x + ha.y * ha.y + ha.z * ha.z + ha.w * ha.w
            + hb.x * hb.x + hb.y * hb.y + hb.z * hb.z + hb.w * hb.w;
#pragma unroll
    for (int off = 4; off; off >>= 1)
        p += __shfl_down_sync(0xffffffffu, p, off, 8);
    if (q == 0) g_nh[v] = p;
}

__global__ __launch_bounds__(256) void k_pass2() {
    int t = blockIdx.x * 256 + threadIdx.x;
    int v = t >> 3, q = t & 7;
    if (v >= NN) return;
    int start = g_offd[v], end = g_offd[v + 1];
    float4 A0 = make_float4(0,0,0,0), A1 = make_float4(0,0,0,0);
    float es = 0.f;
    int i = start;
    for (; i + 1 < end; i += 2) {
        int i0 = g_csrd[i], i1 = g_csrd[i + 1];
        const float4* p0 = (const float4*)(g_h + i0 * DO + q * 8);
        const float4* p1 = (const float4*)(g_h + i1 * DO + q * 8);
        float4 u0 = p0[0], u1 = p0[1];
        float4 w0 = p1[0], w1 = p1[1];
        A0.x += u0.x + w0.x; A0.y += u0.y + w0.y;
        A0.z += u0.z + w0.z; A0.w += u0.w + w0.w;
        A1.x += u1.x + w1.x; A1.y += u1.y + w1.y;
        A1.z += u1.z + w1.z; A1.w += u1.w + w1.w;
        if (q == 0) es += g_nh[i0] + g_nh[i1];
    }
    if (i < end) {
        int i0 = g_csrd[i];
        const float4* p0 = (const float4*)(g_h + i0 * DO + q * 8);
        float4 u0 = p0[0], u1 = p0[1];
        A0.x += u0.x; A0.y += u0.y; A0.z += u0.z; A0.w += u0.w;
        A1.x += u1.x; A1.y += u1.y; A1.z += u1.z; A1.w += u1.w;
        if (q == 0) es += g_nh[i0];
    }
    float4* Ap = (float4*)(g_A + v * DO + q * 8);
    Ap[0] = A0; Ap[1] = A1;
    const float4* hp = (const float4*)(g_h + v * DO + q * 8);
    float4 ha = hp[0], hb = hp[1];
    float p = ha.x * A0.x + ha.y * A0.y + ha.z * A0.z + ha.w * A0.w
            + hb.x * A1.x + hb.y * A1.y + hb.z * A1.z + hb.w * A1.w;
#pragma unroll
    for (int off = 4; off; off >>= 1)
        p += __shfl_down_sync(0xffffffffu, p, off, 8);
    if (q == 0)
        g_e[v] = (float)g_degd[v] * g_nh[v] - 2.f * p + es;
}

// ---------------- online softmax scalars --------------------------------------
__device__ __forceinline__ void triple_merge(float& m, float& z, float& t,
                                             float m2, float z2, float t2) {
    float M = fmaxf(m, m2);
    float a = expf(m - M), c = expf(m2 - M);
    z = z * a + z2 * c;
    t = t * a + t2 * c;
    m = M;
}

__global__ __launch_bounds__(256) void k_sum(const float* __restrict__ temp) {
    float tmp = temp[0];
    float m = -1e30f, z = 0.f, t = 0.f;
    for (int i = blockIdx.x * 256 + threadIdx.x; i < NN; i += NSUMB * 256) {
        float s = -g_e[i] / tmp;
        float M = fmaxf(m, s);
        float a = expf(m - M), c = expf(s - M);
        z = z * a + c;
        t = t * a + s * c;
        m = M;
    }
    __shared__ float sm[256], sz[256], st[256];
    sm[threadIdx.x] = m; sz[threadIdx.x] = z; st[threadIdx.x] = t;
    __syncthreads();
    for (int o = 128; o; o >>= 1) {
        if (threadIdx.x < o) {
            float mm = sm[threadIdx.x], zz = sz[threadIdx.x], tt = st[threadIdx.x];
            triple_merge(mm, zz, tt, sm[threadIdx.x + o], sz[threadIdx.x + o], st[threadIdx.x + o]);
            sm[threadIdx.x] = mm; sz[threadIdx.x] = zz; st[threadIdx.x] = tt;
        }
        __syncthreads();
    }
    if (threadIdx.x == 0) {
        g_pm[blockIdx.x] = sm[0]; g_pz[blockIdx.x] = sz[0]; g_pt[blockIdx.x] = st[0];
    }
}

__global__ __launch_bounds__(256) void k_q(const float* __restrict__ temp) {
    __shared__ float sm[256], sz[256], st[256];
    int tx = threadIdx.x;
    sm[tx] = g_pm[tx]; sz[tx] = g_pz[tx]; st[tx] = g_pt[tx];
    __syncthreads();
    for (int o = 128; o; o >>= 1) {
        if (tx < o) {
            float mm = sm[tx], zz = sz[tx], tt = st[tx];
            triple_merge(mm, zz, tt, sm[tx + o], sz[tx + o], st[tx + o]);
            sm[tx] = mm; sz[tx] = zz; st[tx] = tt;
        }
        __syncthreads();
    }
    float M = sm[0], Z = sz[0], T = st[0];
    float invZ = 1.f / Z;
    float L = M + logf(Z);
    float H = L - T * invZ;
    int v = blockIdx.x * 256 + tx;
    if (v >= NN) return;
    float tmp = temp[0];
    float s = -g_e[v] / tmp;
    g_q[v] = expf(s - M) * invZ * (s - L + H);
}

// pass3 + final (8 lanes per node)
__global__ __launch_bounds__(256) void k_pass3(const float* __restrict__ wgt,
                                               float* __restrict__ out) {
    int t = blockIdx.x * 256 + threadIdx.x;
    int v = t >> 3, q = t & 7;
    if (v >= NN) return;
    int start = g_offs[v], end = g_offs[v + 1];
    float4 B0 = make_float4(0,0,0,0), B1 = make_float4(0,0,0,0);
    float Qs = 0.f;
    int i = start;
    for (; i + 1 < end; i += 2) {
        int i0 = g_csrs[i], i1 = g_csrs[i + 1];
        float q0 = g_q[i0], q1 = g_q[i1];
        const float4* p0 = (const float4*)(g_h + i0 * DO + q * 8);
        const float4* p1 = (const float4*)(g_h + i1 * DO + q * 8);
        float4 u0 = p0[0], u1 = p0[1];
        float4 w0 = p1[0], w1 = p1[1];
        B0.x += q0 * u0.x + q1 * w0.x; B0.y += q0 * u0.y + q1 * w0.y;
        B0.z += q0 * u0.z + q1 * w0.z; B0.w += q0 * u0.w + q1 * w0.w;
        B1.x += q0 * u1.x + q1 * w1.x; B1.y += q0 * u1.y + q1 * w1.y;
        B1.z += q0 * u1.z + q1 * w1.z; B1.w += q0 * u1.w + q1 * w1.w;
        Qs += q0 + q1;
    }
    if (i < end) {
        int i0 = g_csrs[i];
        float q0 = g_q[i0];
        const float4* p0 = (const float4*)(g_h + i0 * DO + q * 8);
        float4 u0 = p0[0], u1 = p0[1];
        B0.x += q0 * u0.x; B0.y += q0 * u0.y; B0.z += q0 * u0.z; B0.w += q0 * u0.w;
        B1.x += q0 * u1.x; B1.y += q0 * u1.y; B1.z += q0 * u1.z; B1.w += q0 * u1.w;
        Qs += q0;
    }
    const float4* hp = (const float4*)(g_h + v * DO + q * 8);
    const float4* Ap = (const float4*)(g_A + v * DO + q * 8);
    float4 ha = hp[0], hb = hp[1];
    float4 Aa = Ap[0], Ab = Ap[1];
    float qv = g_q[v];
    float dg = (float)g_degd[v];
    float w2 = 2.f * wgt[0];
    float4 oa, ob;
    oa.x = ha.x + w2 * (qv * (dg * ha.x - Aa.x) + Qs * ha.x - B0.x);
    oa.y = ha.y + w2 * (qv * (dg * ha.y - Aa.y) + Qs * ha.y - B0.y);
    oa.z = ha.z + w2 * (qv * (dg * ha.z - Aa.z) + Qs * ha.z - B0.z);
    oa.w = ha.w + w2 * (qv * (dg * ha.w - Aa.w) + Qs * ha.w - B0.w);
    ob.x = hb.x + w2 * (qv * (dg * hb.x - Ab.x) + Qs * hb.x - B1.x);
    ob.y = hb.y + w2 * (qv * (dg * hb.y - Ab.y) + Qs * hb.y - B1.y);
    ob.z = hb.z + w2 * (qv * (dg * hb.z - Ab.z) + Qs * hb.z - B1.z);
    ob.w = hb.w + w2 * (qv * (dg * hb.w - Ab.w) + Qs * hb.w - B1.w);
    float4* op = (float4*)(out + v * DO + q * 8);
    op[0] = oa; op[1] = ob;
}

// ---------------- launch ----------------------------------------------------
extern "C" void kernel_launch(void* const* d_in, const int* in_sizes, int n_in,
                              void* d_out, int out_size) {
    const float* x    = (const float*)d_in[0];
    const int*   ei   = (const int*)d_in[1];
    const float* wgt  = (const float*)d_in[2];
    const float* temp = (const float*)d_in[3];
    const float* W    = (const float*)d_in[4];
    const float* b    = (const float*)d_in[5];
    float* out = (float*)d_out;

    static cudaStream_t s2 = nullptr, s3 = nullptr;
    static cudaEvent_t evA = nullptr, evB = nullptr, evC = nullptr, evD = nullptr;
    if (s2 == nullptr) {
        cudaStreamCreateWithFlags(&s2, cudaStreamNonBlocking);
        cudaStreamCreateWithFlags(&s3, cudaStreamNonBlocking);
        cudaEventCreateWithFlags(&evA, cudaEventDisableTiming);
        cudaEventCreateWithFlags(&evB, cudaEventDisableTiming);
        cudaEventCreateWithFlags(&evC, cudaEventDisableTiming);
        cudaEventCreateWithFlags(&evD, cudaEventDisableTiming);
    }

    const int NB_E  = (NE + 255) / 256;
    const int NB_N  = (NN + 255) / 256;
    const int NB_N8 = (NN * 8 + 255) / 256;

    // fork: GEMM on side stream s2
    cudaEventRecord(evA, 0);
    cudaStreamWaitEvent(s2, evA, 0);
    k_gemm<<<(NN + 127) / 128, 128, 0, s2>>>(x, W);
    cudaEventRecord(evB, s2);

    // CSR build on main stream
    k_zero<<<NB_N, 256>>>();
    k_deg<<<NB_E, 256>>>(ei);
    k_scan<<<NBLK_SCAN, SB>>>();
    cudaEventRecord(evD, 0);
    k_fill_d<<<NB_E, 256>>>(ei);

    // src-CSR fill on s3, overlapped with pass1/pass2
    cudaStreamWaitEvent(s3, evD, 0);
    k_fill_s<<<NB_E, 256, 0, s3>>>(ei);
    cudaEventRecord(evC, s3);

    // join GEMM
    cudaStreamWaitEvent(0, evB, 0);
    k_pass1<<<NB_N8, 256>>>(b);
    k_pass2<<<NB_N8, 256>>>();
    k_sum<<<NSUMB, 256>>>(temp);
    k_q<<<NB_N, 256>>>(temp);

    // join src-CSR
    cudaStreamWaitEvent(0, evC, 0);
    k_pass3<<<NB_N8, 256>>>(wgt, out);
}

// round 7
// speedup vs baseline: 1.0439x; 1.0439x over previous
#include <cuda_runtime.h>

#define NN 100000
#define NE 1000000
#define DI 128
#define DO 64
#define SB 1024
#define NBLK_SCAN ((NN + SB - 1) / SB)   // 98
#define NSUMB 256

// ---------------- scratch (device globals) ----------------------------------
__device__ float g_h0[NN * DO];
__device__ float g_h [NN * DO];
__device__ float g_A [NN * DO];
__device__ int   g_degd[NN];
__device__ int   g_degs[NN];
__device__ int   g_offd[NN + 1];
__device__ int   g_offs[NN + 1];
__device__ int   g_curd[NN];
__device__ int   g_curs[NN];
__device__ int   g_csrd[NE];
__device__ int   g_csrs[NE];
__device__ int   g_bsumd[NBLK_SCAN + 1];
__device__ int   g_bsums[NBLK_SCAN + 1];
__device__ float g_e[NN];
__device__ float g_nh[NN];
__device__ float g_q[NN];
__device__ float g_dinv[NN];
__device__ float g_pm[NSUMB];
__device__ float g_pz[NSUMB];
__device__ float g_pt[NSUMB];

// ---------------- CSR build --------------------------------------------------
__global__ __launch_bounds__(256) void k_zero() {
    int i = blockIdx.x * 256 + threadIdx.x;
    if (i < NN) { g_degd[i] = 0; g_degs[i] = 0; }
}

__global__ __launch_bounds__(256) void k_deg(const int* __restrict__ ei) {
    int e = blockIdx.x * 256 + threadIdx.x;
    if (e >= NE) return;
    atomicAdd(&g_degs[ei[e]], 1);
    atomicAdd(&g_degd[ei[NE + e]], 1);
}

__global__ __launch_bounds__(SB) void k_scan1() {
    __shared__ int sd[SB], ss[SB];
    int t = threadIdx.x;
    int i = blockIdx.x * SB + t;
    int a = (i < NN) ? g_degd[i] : 0;
    int b = (i < NN) ? g_degs[i] : 0;
    sd[t] = a; ss[t] = b;
    __syncthreads();
    for (int o = 1; o < SB; o <<= 1) {
        int va = (t >= o) ? sd[t - o] : 0;
        int vb = (t >= o) ? ss[t - o] : 0;
        __syncthreads();
        sd[t] += va; ss[t] += vb;
        __syncthreads();
    }
    if (i < NN) { g_offd[i] = sd[t] - a; g_offs[i] = ss[t] - b; }
    if (t == SB - 1) { g_bsumd[blockIdx.x] = sd[t]; g_bsums[blockIdx.x] = ss[t]; }
}

__global__ __launch_bounds__(128) void k_scan2() {
    __shared__ int sd[128], ss[128];
    int t = threadIdx.x;
    int a = (t < NBLK_SCAN) ? g_bsumd[t] : 0;
    int b = (t < NBLK_SCAN) ? g_bsums[t] : 0;
    sd[t] = a; ss[t] = b;
    __syncthreads();
    for (int o = 1; o < 128; o <<= 1) {
        int va = (t >= o) ? sd[t - o] : 0;
        int vb = (t >= o) ? ss[t - o] : 0;
        __syncthreads();
        sd[t] += va; ss[t] += vb;
        __syncthreads();
    }
    if (t < NBLK_SCAN) { g_bsumd[t] = sd[t] - a; g_bsums[t] = ss[t] - b; }
}

__global__ __launch_bounds__(256) void k_scan3() {
    int i = blockIdx.x * 256 + threadIdx.x;
    if (i < NN) {
        int od = g_offd[i] + g_bsumd[i / SB];
        int os = g_offs[i] + g_bsums[i / SB];
        g_offd[i] = od; g_curd[i] = od;
        g_offs[i] = os; g_curs[i] = os;
        g_dinv[i] = rsqrtf((float)(g_degd[i] + 1));
    }
    if (i == 0) { g_offd[NN] = NE; g_offs[NN] = NE; }
}

__global__ __launch_bounds__(256) void k_fill_d(const int* __restrict__ ei) {
    int e = blockIdx.x * 256 + threadIdx.x;
    if (e >= NE) return;
    int s = ei[e], d = ei[NE + e];
    int pd = atomicAdd(&g_curd[d], 1);
    g_csrd[pd] = s;
}

__global__ __launch_bounds__(256) void k_fill_s(const int* __restrict__ ei) {
    int e = blockIdx.x * 256 + threadIdx.x;
    if (e >= NE) return;
    int s = ei[e], d = ei[NE + e];
    int ps = atomicAdd(&g_curs[s], 1);
    g_csrs[ps] = d;
}

// ---------------- GEMM: h0 = x @ W (128 rows/block, 8x8 per thread) ----------
__global__ __launch_bounds__(128) void k_gemm(const float* __restrict__ x,
                                              const float* __restrict__ W) {
    __shared__ float Ws[DI * DO];
    __shared__ float xs[16 * 128];
    int t = threadIdx.x;
    int row0 = blockIdx.x * 128;
    for (int i = t * 4; i < DI * DO; i += 128 * 4)
        *(float4*)(Ws + i) = *(const float4*)(W + i);

    int cg = t & 7, rt = t >> 3;
    float acc[8][8];
#pragma unroll
    for (int i = 0; i < 8; i++)
#pragma unroll
        for (int j = 0; j < 8; j++) acc[i][j] = 0.f;

    int grow = row0 + t;
    bool rok = grow < NN;

    for (int kc = 0; kc < 8; kc++) {
        __syncthreads();
        float4 xa = rok ? *(const float4*)(x + grow * DI + kc * 16 + 0)  : make_float4(0,0,0,0);
        float4 xb = rok ? *(const float4*)(x + grow * DI + kc * 16 + 4)  : make_float4(0,0,0,0);
        float4 xc = rok ? *(const float4*)(x + grow * DI + kc * 16 + 8)  : make_float4(0,0,0,0);
        float4 xd = rok ? *(const float4*)(x + grow * DI + kc * 16 + 12) : make_float4(0,0,0,0);
        xs[0*128+t]=xa.x;  xs[1*128+t]=xa.y;  xs[2*128+t]=xa.z;  xs[3*128+t]=xa.w;
        xs[4*128+t]=xb.x;  xs[5*128+t]=xb.y;  xs[6*128+t]=xb.z;  xs[7*128+t]=xb.w;
        xs[8*128+t]=xc.x;  xs[9*128+t]=xc.y;  xs[10*128+t]=xc.z; xs[11*128+t]=xc.w;
        xs[12*128+t]=xd.x; xs[13*128+t]=xd.y; xs[14*128+t]=xd.z; xs[15*128+t]=xd.w;
        __syncthreads();
#pragma unroll
        for (int k = 0; k < 16; k++) {
            float4 x0 = *(const float4*)(xs + k * 128 + rt * 8);
            float4 x1 = *(const float4*)(xs + k * 128 + rt * 8 + 4);
            float4 w0 = *(const float4*)(Ws + (kc * 16 + k) * DO + cg * 8);
            float4 w1 = *(const float4*)(Ws + (kc * 16 + k) * DO + cg * 8 + 4);
            float xv[8] = {x0.x, x0.y, x0.z, x0.w, x1.x, x1.y, x1.z, x1.w};
            float wv[8] = {w0.x, w0.y, w0.z, w0.w, w1.x, w1.y, w1.z, w1.w};
#pragma unroll
            for (int i = 0; i < 8; i++)
#pragma unroll
                for (int j = 0; j < 8; j++)
                    acc[i][j] += xv[i] * wv[j];
        }
    }
#pragma unroll
    for (int i = 0; i < 8; i++) {
        int gr = row0 + rt * 8 + i;
        if (gr < NN) {
            float4* p = (float4*)(g_h0 + gr * DO + cg * 8);
            p[0] = make_float4(acc[i][0], acc[i][1], acc[i][2], acc[i][3]);
            p[1] = make_float4(acc[i][4], acc[i][5], acc[i][6], acc[i][7]);
        }
    }
}

// ---------------- gather passes (8 lanes per node, 2 float4 per lane) ---------
__global__ __launch_bounds__(256) void k_pass1(const float* __restrict__ b) {
    int t = blockIdx.x * 256 + threadIdx.x;
    int v = t >> 3, q = t & 7;
    if (v >= NN) return;
    int start = g_offd[v], end = g_offd[v + 1];
    float4 A0 = make_float4(0,0,0,0), A1 = make_float4(0,0,0,0);
    int i = start;
    for (; i + 1 < end; i += 2) {
        int i0 = g_csrd[i], i1 = g_csrd[i + 1];
        float d0 = g_dinv[i0], d1 = g_dinv[i1];
        const float4* p0 = (const float4*)(g_h0 + i0 * DO + q * 8);
        const float4* p1 = (const float4*)(g_h0 + i1 * DO + q * 8);
        float4 u0 = p0[0], u1 = p0[1];
        float4 w0 = p1[0], w1 = p1[1];
        A0.x += u0.x * d0 + w0.x * d1; A0.y += u0.y * d0 + w0.y * d1;
        A0.z += u0.z * d0 + w0.z * d1; A0.w += u0.w * d0 + w0.w * d1;
        A1.x += u1.x * d0 + w1.x * d1; A1.y += u1.y * d0 + w1.y * d1;
        A1.z += u1.z * d0 + w1.z * d1; A1.w += u1.w * d0 + w1.w * d1;
    }
    if (i < end) {
        int i0 = g_csrd[i];
        float d0 = g_dinv[i0];
        const float4* p0 = (const float4*)(g_h0 + i0 * DO + q * 8);
        float4 u0 = p0[0], u1 = p0[1];
        A0.x += u0.x * d0; A0.y += u0.y * d0; A0.z += u0.z * d0; A0.w += u0.w * d0;
        A1.x += u1.x * d0; A1.y += u1.y * d0; A1.z += u1.z * d0; A1.w += u1.w * d0;
    }
    float dv = g_dinv[v];
    float dv2 = dv * dv;
    const float4* h0p = (const float4*)(g_h0 + v * DO + q * 8);
    float4 h0a = h0p[0], h0b = h0p[1];
    const float4* bp = (const float4*)(b + q * 8);
    float4 ba = bp[0], bb = bp[1];
    float4 ha, hb;
    ha.x = dv * A0.x + dv2 * h0a.x + ba.x;
    ha.y = dv * A0.y + dv2 * h0a.y + ba.y;
    ha.z = dv * A0.z + dv2 * h0a.z + ba.z;
    ha.w = dv * A0.w + dv2 * h0a.w + ba.w;
    hb.x = dv * A1.x + dv2 * h0b.x + bb.x;
    hb.y = dv * A1.y + dv2 * h0b.y + bb.y;
    hb.z = dv * A1.z + dv2 * h0b.z + bb.z;
    hb.w = dv * A1.w + dv2 * h0b.w + bb.w;
    float4* hp = (float4*)(g_h + v * DO + q * 8);
    hp[0] = ha; hp[1] = hb;
    float p = ha.x * ha.x + ha.y * ha.y + ha.z * ha.z + ha.w * ha.w
            + hb.x * hb.x + hb.y * hb.y + hb.z * hb.z + hb.w * hb.w;
#pragma unroll
    for (int off = 4; off; off >>= 1)
        p += __shfl_down_sync(0xffffffffu, p, off, 8);
    if (q == 0) g_nh[v] = p;
}

__global__ __launch_bounds__(256) void k_pass2() {
    int t = blockIdx.x * 256 + threadIdx.x;
    int v = t >> 3, q = t & 7;
    if (v >= NN) return;
    int start = g_offd[v], end = g_offd[v + 1];
    float4 A0 = make_float4(0,0,0,0), A1 = make_float4(0,0,0,0);
    float es = 0.f;
    int i = start;
    for (; i + 1 < end; i += 2) {
        int i0 = g_csrd[i], i1 = g_csrd[i + 1];
        const float4* p0 = (const float4*)(g_h + i0 * DO + q * 8);
        const float4* p1 = (const float4*)(g_h + i1 * DO + q * 8);
        float4 u0 = p0[0], u1 = p0[1];
        float4 w0 = p1[0], w1 = p1[1];
        A0.x += u0.x + w0.x; A0.y += u0.y + w0.y;
        A0.z += u0.z + w0.z; A0.w += u0.w + w0.w;
        A1.x += u1.x + w1.x; A1.y += u1.y + w1.y;
        A1.z += u1.z + w1.z; A1.w += u1.w + w1.w;
        if (q == 0) es += g_nh[i0] + g_nh[i1];
    }
    if (i < end) {
        int i0 = g_csrd[i];
        const float4* p0 = (const float4*)(g_h + i0 * DO + q * 8);
        float4 u0 = p0[0], u1 = p0[1];
        A0.x += u0.x; A0.y += u0.y; A0.z += u0.z; A0.w += u0.w;
        A1.x += u1.x; A1.y += u1.y; A1.z += u1.z; A1.w += u1.w;
        if (q == 0) es += g_nh[i0];
    }
    float4* Ap = (float4*)(g_A + v * DO + q * 8);
    Ap[0] = A0; Ap[1] = A1;
    const float4* hp = (const float4*)(g_h + v * DO + q * 8);
    float4 ha = hp[0], hb = hp[1];
    float p = ha.x * A0.x + ha.y * A0.y + ha.z * A0.z + ha.w * A0.w
            + hb.x * A1.x + hb.y * A1.y + hb.z * A1.z + hb.w * A1.w;
#pragma unroll
    for (int off = 4; off; off >>= 1)
        p += __shfl_down_sync(0xffffffffu, p, off, 8);
    if (q == 0)
        g_e[v] = (float)g_degd[v] * g_nh[v] - 2.f * p + es;
}

// ---------------- online softmax scalars --------------------------------------
__device__ __forceinline__ void triple_merge(float& m, float& z, float& t,
                                             float m2, float z2, float t2) {
    float M = fmaxf(m, m2);
    float a = expf(m - M), c = expf(m2 - M);
    z = z * a + z2 * c;
    t = t * a + t2 * c;
    m = M;
}

__global__ __launch_bounds__(256) void k_sum(const float* __restrict__ temp) {
    float tmp = temp[0];
    float m = -1e30f, z = 0.f, t = 0.f;
    for (int i = blockIdx.x * 256 + threadIdx.x; i < NN; i += NSUMB * 256) {
        float s = -g_e[i] / tmp;
        float M = fmaxf(m, s);
        float a = expf(m - M), c = expf(s - M);
        z = z * a + c;
        t = t * a + s * c;
        m = M;
    }
    __shared__ float sm[256], sz[256], st[256];
    sm[threadIdx.x] = m; sz[threadIdx.x] = z; st[threadIdx.x] = t;
    __syncthreads();
    for (int o = 128; o; o >>= 1) {
        if (threadIdx.x < o) {
            float mm = sm[threadIdx.x], zz = sz[threadIdx.x], tt = st[threadIdx.x];
            triple_merge(mm, zz, tt, sm[threadIdx.x + o], sz[threadIdx.x + o], st[threadIdx.x + o]);
            sm[threadIdx.x] = mm; sz[threadIdx.x] = zz; st[threadIdx.x] = tt;
        }
        __syncthreads();
    }
    if (threadIdx.x == 0) {
        g_pm[blockIdx.x] = sm[0]; g_pz[blockIdx.x] = sz[0]; g_pt[blockIdx.x] = st[0];
    }
}

__global__ __launch_bounds__(256) void k_q(const float* __restrict__ temp) {
    __shared__ float sm[256], sz[256], st[256];
    int tx = threadIdx.x;
    sm[tx] = g_pm[tx]; sz[tx] = g_pz[tx]; st[tx] = g_pt[tx];
    __syncthreads();
    for (int o = 128; o; o >>= 1) {
        if (tx < o) {
            float mm = sm[tx], zz = sz[tx], tt = st[tx];
            triple_merge(mm, zz, tt, sm[tx + o], sz[tx + o], st[tx + o]);
            sm[tx] = mm; sz[tx] = zz; st[tx] = tt;
        }
        __syncthreads();
    }
    float M = sm[0], Z = sz[0], T = st[0];
    float invZ = 1.f / Z;
    float L = M + logf(Z);
    float H = L - T * invZ;
    int v = blockIdx.x * 256 + tx;
    if (v >= NN) return;
    float tmp = temp[0];
    float s = -g_e[v] / tmp;
    g_q[v] = expf(s - M) * invZ * (s - L + H);
}

// pass3 + final (8 lanes per node)
__global__ __launch_bounds__(256) void k_pass3(const float* __restrict__ wgt,
                                               float* __restrict__ out) {
    int t = blockIdx.x * 256 + threadIdx.x;
    int v = t >> 3, q = t & 7;
    if (v >= NN) return;
    int start = g_offs[v], end = g_offs[v + 1];
    float4 B0 = make_float4(0,0,0,0), B1 = make_float4(0,0,0,0);
    float Qs = 0.f;
    int i = start;
    for (; i + 1 < end; i += 2) {
        int i0 = g_csrs[i], i1 = g_csrs[i + 1];
        float q0 = g_q[i0], q1 = g_q[i1];
        const float4* p0 = (const float4*)(g_h + i0 * DO + q * 8);
        const float4* p1 = (const float4*)(g_h + i1 * DO + q * 8);
        float4 u0 = p0[0], u1 = p0[1];
        float4 w0 = p1[0], w1 = p1[1];
        B0.x += q0 * u0.x + q1 * w0.x; B0.y += q0 * u0.y + q1 * w0.y;
        B0.z += q0 * u0.z + q1 * w0.z; B0.w += q0 * u0.w + q1 * w0.w;
        B1.x += q0 * u1.x + q1 * w1.x; B1.y += q0 * u1.y + q1 * w1.y;
        B1.z += q0 * u1.z + q1 * w1.z; B1.w += q0 * u1.w + q1 * w1.w;
        Qs += q0 + q1;
    }
    if (i < end) {
        int i0 = g_csrs[i];
        float q0 = g_q[i0];
        const float4* p0 = (const float4*)(g_h + i0 * DO + q * 8);
        float4 u0 = p0[0], u1 = p0[1];
        B0.x += q0 * u0.x; B0.y += q0 * u0.y; B0.z += q0 * u0.z; B0.w += q0 * u0.w;
        B1.x += q0 * u1.x; B1.y += q0 * u1.y; B1.z += q0 * u1.z; B1.w += q0 * u1.w;
        Qs += q0;
    }
    const float4* hp = (const float4*)(g_h + v * DO + q * 8);
    const float4* Ap = (const float4*)(g_A + v * DO + q * 8);
    float4 ha = hp[0], hb = hp[1];
    float4 Aa = Ap[0], Ab = Ap[1];
    float qv = g_q[v];
    float dg = (float)g_degd[v];
    float w2 = 2.f * wgt[0];
    float4 oa, ob;
    oa.x = ha.x + w2 * (qv * (dg * ha.x - Aa.x) + Qs * ha.x - B0.x);
    oa.y = ha.y + w2 * (qv * (dg * ha.y - Aa.y) + Qs * ha.y - B0.y);
    oa.z = ha.z + w2 * (qv * (dg * ha.z - Aa.z) + Qs * ha.z - B0.z);
    oa.w = ha.w + w2 * (qv * (dg * ha.w - Aa.w) + Qs * ha.w - B0.w);
    ob.x = hb.x + w2 * (qv * (dg * hb.x - Ab.x) + Qs * hb.x - B1.x);
    ob.y = hb.y + w2 * (qv * (dg * hb.y - Ab.y) + Qs * hb.y - B1.y);
    ob.z = hb.z + w2 * (qv * (dg * hb.z - Ab.z) + Qs * hb.z - B1.z);
    ob.w = hb.w + w2 * (qv * (dg * hb.w - Ab.w) + Qs * hb.w - B1.w);
    float4* op = (float4*)(out + v * DO + q * 8);
    op[0] = oa; op[1] = ob;
}

// ---------------- launch ----------------------------------------------------
extern "C" void kernel_launch(void* const* d_in, const int* in_sizes, int n_in,
                              void* d_out, int out_size) {
    const float* x    = (const float*)d_in[0];
    const int*   ei   = (const int*)d_in[1];
    const float* wgt  = (const float*)d_in[2];
    const float* temp = (const float*)d_in[3];
    const float* W    = (const float*)d_in[4];
    const float* b    = (const float*)d_in[5];
    float* out = (float*)d_out;

    static cudaStream_t s2 = nullptr, s3 = nullptr;
    static cudaEvent_t evA = nullptr, evB = nullptr, evC = nullptr, evD = nullptr;
    if (s2 == nullptr) {
        cudaStreamCreateWithFlags(&s2, cudaStreamNonBlocking);
        cudaStreamCreateWithFlags(&s3, cudaStreamNonBlocking);
        cudaEventCreateWithFlags(&evA, cudaEventDisableTiming);
        cudaEventCreateWithFlags(&evB, cudaEventDisableTiming);
        cudaEventCreateWithFlags(&evC, cudaEventDisableTiming);
        cudaEventCreateWithFlags(&evD, cudaEventDisableTiming);
    }

    const int NB_E  = (NE + 255) / 256;
    const int NB_N  = (NN + 255) / 256;
    const int NB_N8 = (NN * 8 + 255) / 256;

    // fork: GEMM on side stream s2
    cudaEventRecord(evA, 0);
    cudaStreamWaitEvent(s2, evA, 0);
    k_gemm<<<(NN + 127) / 128, 128, 0, s2>>>(x, W);
    cudaEventRecord(evB, s2);

    // CSR build on main stream
    k_zero<<<NB_N, 256>>>();
    k_deg<<<NB_E, 256>>>(ei);
    k_scan1<<<NBLK_SCAN, SB>>>();
    k_scan2<<<1, 128>>>();
    k_scan3<<<NB_N, 256>>>();
    cudaEventRecord(evD, 0);
    k_fill_d<<<NB_E, 256>>>(ei);

    // src-CSR fill on s3, overlapped with pass1/pass2
    cudaStreamWaitEvent(s3, evD, 0);
    k_fill_s<<<NB_E, 256, 0, s3>>>(ei);
    cudaEventRecord(evC, s3);

    // join GEMM
    cudaStreamWaitEvent(0, evB, 0);
    k_pass1<<<NB_N8, 256>>>(b);
    k_pass2<<<NB_N8, 256>>>();
    k_sum<<<NSUMB, 256>>>(temp);
    k_q<<<NB_N, 256>>>(temp);

    // join src-CSR
    cudaStreamWaitEvent(0, evC, 0);
    k_pass3<<<NB_N8, 256>>>(wgt, out);
}

// round 8
// speedup vs baseline: 1.0915x; 1.0456x over previous
#include <cuda_runtime.h>

#define NN 100000
#define NE 1000000
#define DI 128
#define DO 64
#define SB 1024
#define NBLK_SCAN ((NN + SB - 1) / SB)   // 98
#define NSUMB 256

// ---------------- scratch (device globals) ----------------------------------
__device__ float g_h0[NN * DO];
__device__ float g_h [NN * DO];
__device__ float g_A [NN * DO];
__device__ int   g_degd[NN];
__device__ int   g_degs[NN];
__device__ int   g_offd[NN + 1];
__device__ int   g_offs[NN + 1];
__device__ int   g_curd[NN];
__device__ int   g_curs[NN];
__device__ int   g_csrd[NE];
__device__ int   g_csrs[NE];
__device__ int   g_bsumd[NBLK_SCAN + 1];
__device__ int   g_bsums[NBLK_SCAN + 1];
__device__ float g_e[NN];
__device__ float g_nh[NN];
__device__ float g_q[NN];
__device__ float g_dinv[NN];
__device__ float g_pm[NSUMB];
__device__ float g_pz[NSUMB];
__device__ float g_pt[NSUMB];

// ---------------- CSR build --------------------------------------------------
__global__ __launch_bounds__(256) void k_zero() {
    int i = blockIdx.x * 256 + threadIdx.x;
    if (i < NN) { g_degd[i] = 0; g_degs[i] = 0; }
}

// 2 edges per thread
__global__ __launch_bounds__(256) void k_deg(const int* __restrict__ ei) {
    int e2 = blockIdx.x * 256 + threadIdx.x;
    int e = e2 * 2;
    if (e + 1 < NE) {
        int2 s = *(const int2*)(ei + e);
        int2 d = *(const int2*)(ei + NE + e);
        atomicAdd(&g_degs[s.x], 1);
        atomicAdd(&g_degs[s.y], 1);
        atomicAdd(&g_degd[d.x], 1);
        atomicAdd(&g_degd[d.y], 1);
    } else if (e < NE) {
        atomicAdd(&g_degs[ei[e]], 1);
        atomicAdd(&g_degd[ei[NE + e]], 1);
    }
}

__global__ __launch_bounds__(SB) void k_scan1() {
    __shared__ int sd[SB], ss[SB];
    int t = threadIdx.x;
    int i = blockIdx.x * SB + t;
    int a = (i < NN) ? g_degd[i] : 0;
    int b = (i < NN) ? g_degs[i] : 0;
    sd[t] = a; ss[t] = b;
    __syncthreads();
    for (int o = 1; o < SB; o <<= 1) {
        int va = (t >= o) ? sd[t - o] : 0;
        int vb = (t >= o) ? ss[t - o] : 0;
        __syncthreads();
        sd[t] += va; ss[t] += vb;
        __syncthreads();
    }
    if (i < NN) { g_offd[i] = sd[t] - a; g_offs[i] = ss[t] - b; }
    if (t == SB - 1) { g_bsumd[blockIdx.x] = sd[t]; g_bsums[blockIdx.x] = ss[t]; }
}

__global__ __launch_bounds__(128) void k_scan2() {
    __shared__ int sd[128], ss[128];
    int t = threadIdx.x;
    int a = (t < NBLK_SCAN) ? g_bsumd[t] : 0;
    int b = (t < NBLK_SCAN) ? g_bsums[t] : 0;
    sd[t] = a; ss[t] = b;
    __syncthreads();
    for (int o = 1; o < 128; o <<= 1) {
        int va = (t >= o) ? sd[t - o] : 0;
        int vb = (t >= o) ? ss[t - o] : 0;
        __syncthreads();
        sd[t] += va; ss[t] += vb;
        __syncthreads();
    }
    if (t < NBLK_SCAN) { g_bsumd[t] = sd[t] - a; g_bsums[t] = ss[t] - b; }
}

__global__ __launch_bounds__(256) void k_scan3() {
    int i = blockIdx.x * 256 + threadIdx.x;
    if (i < NN) {
        int od = g_offd[i] + g_bsumd[i / SB];
        int os = g_offs[i] + g_bsums[i / SB];
        g_offd[i] = od; g_curd[i] = od;
        g_offs[i] = os; g_curs[i] = os;
        g_dinv[i] = rsqrtf((float)(g_degd[i] + 1));
    }
    if (i == 0) { g_offd[NN] = NE; g_offs[NN] = NE; }
}

__global__ __launch_bounds__(256) void k_fill_d(const int* __restrict__ ei) {
    int e = blockIdx.x * 256 + threadIdx.x;
    if (e >= NE) return;
    int s = ei[e], d = ei[NE + e];
    int pd = atomicAdd(&g_curd[d], 1);
    g_csrd[pd] = s;
}

__global__ __launch_bounds__(256) void k_fill_s(const int* __restrict__ ei) {
    int e = blockIdx.x * 256 + threadIdx.x;
    if (e >= NE) return;
    int s = ei[e], d = ei[NE + e];
    int ps = atomicAdd(&g_curs[s], 1);
    g_csrs[ps] = d;
}

// ---------------- GEMM: h0 = x @ W (128 rows/block, 8x8 per thread) ----------
__global__ __launch_bounds__(128) void k_gemm(const float* __restrict__ x,
                                              const float* __restrict__ W) {
    __shared__ float Ws[DI * DO];
    __shared__ float xs[16 * 128];
    int t = threadIdx.x;
    int row0 = blockIdx.x * 128;
    for (int i = t * 4; i < DI * DO; i += 128 * 4)
        *(float4*)(Ws + i) = *(const float4*)(W + i);

    int cg = t & 7, rt = t >> 3;
    float acc[8][8];
#pragma unroll
    for (int i = 0; i < 8; i++)
#pragma unroll
        for (int j = 0; j < 8; j++) acc[i][j] = 0.f;

    int grow = row0 + t;
    bool rok = grow < NN;

    for (int kc = 0; kc < 8; kc++) {
        __syncthreads();
        float4 xa = rok ? *(const float4*)(x + grow * DI + kc * 16 + 0)  : make_float4(0,0,0,0);
        float4 xb = rok ? *(const float4*)(x + grow * DI + kc * 16 + 4)  : make_float4(0,0,0,0);
        float4 xc = rok ? *(const float4*)(x + grow * DI + kc * 16 + 8)  : make_float4(0,0,0,0);
        float4 xd = rok ? *(const float4*)(x + grow * DI + kc * 16 + 12) : make_float4(0,0,0,0);
        xs[0*128+t]=xa.x;  xs[1*128+t]=xa.y;  xs[2*128+t]=xa.z;  xs[3*128+t]=xa.w;
        xs[4*128+t]=xb.x;  xs[5*128+t]=xb.y;  xs[6*128+t]=xb.z;  xs[7*128+t]=xb.w;
        xs[8*128+t]=xc.x;  xs[9*128+t]=xc.y;  xs[10*128+t]=xc.z; xs[11*128+t]=xc.w;
        xs[12*128+t]=xd.x; xs[13*128+t]=xd.y; xs[14*128+t]=xd.z; xs[15*128+t]=xd.w;
        __syncthreads();
#pragma unroll
        for (int k = 0; k < 16; k++) {
            float4 x0 = *(const float4*)(xs + k * 128 + rt * 8);
            float4 x1 = *(const float4*)(xs + k * 128 + rt * 8 + 4);
            float4 w0 = *(const float4*)(Ws + (kc * 16 + k) * DO + cg * 8);
            float4 w1 = *(const float4*)(Ws + (kc * 16 + k) * DO + cg * 8 + 4);
            float xv[8] = {x0.x, x0.y, x0.z, x0.w, x1.x, x1.y, x1.z, x1.w};
            float wv[8] = {w0.x, w0.y, w0.z, w0.w, w1.x, w1.y, w1.z, w1.w};
#pragma unroll
            for (int i = 0; i < 8; i++)
#pragma unroll
                for (int j = 0; j < 8; j++)
                    acc[i][j] += xv[i] * wv[j];
        }
    }
#pragma unroll
    for (int i = 0; i < 8; i++) {
        int gr = row0 + rt * 8 + i;
        if (gr < NN) {
            float4* p = (float4*)(g_h0 + gr * DO + cg * 8);
            p[0] = make_float4(acc[i][0], acc[i][1], acc[i][2], acc[i][3]);
            p[1] = make_float4(acc[i][4], acc[i][5], acc[i][6], acc[i][7]);
        }
    }
}

// ---------------- gather passes (16 lanes per node, index prefetch) ----------
__global__ __launch_bounds__(256) void k_pass1(const float* __restrict__ b) {
    int t = blockIdx.x * 256 + threadIdx.x;
    int v = t >> 4, q = t & 15;
    if (v >= NN) return;
    int start = g_offd[v], end = g_offd[v + 1];
    float ax = 0.f, ay = 0.f, az = 0.f, aw = 0.f;
    int idx = (start < end) ? g_csrd[start] : 0;
    for (int i = start; i < end; i++) {
        int nidx = (i + 1 < end) ? g_csrd[i + 1] : 0;
        float ds = g_dinv[idx];
        float4 u = *(const float4*)(g_h0 + idx * DO + q * 4);
        ax += u.x * ds; ay += u.y * ds; az += u.z * ds; aw += u.w * ds;
        idx = nidx;
    }
    float dv = g_dinv[v];
    float dv2 = dv * dv;
    float4 h0v = *(const float4*)(g_h0 + v * DO + q * 4);
    float4 bv  = *(const float4*)(b + q * 4);
    float4 h;
    h.x = dv * ax + dv2 * h0v.x + bv.x;
    h.y = dv * ay + dv2 * h0v.y + bv.y;
    h.z = dv * az + dv2 * h0v.z + bv.z;
    h.w = dv * aw + dv2 * h0v.w + bv.w;
    *(float4*)(g_h + v * DO + q * 4) = h;
    float p = h.x * h.x + h.y * h.y + h.z * h.z + h.w * h.w;
#pragma unroll
    for (int off = 8; off; off >>= 1)
        p += __shfl_down_sync(0xffffffffu, p, off, 16);
    if (q == 0) g_nh[v] = p;
}

__global__ __launch_bounds__(256) void k_pass2() {
    int t = blockIdx.x * 256 + threadIdx.x;
    int v = t >> 4, q = t & 15;
    if (v >= NN) return;
    int start = g_offd[v], end = g_offd[v + 1];
    float ax = 0.f, ay = 0.f, az = 0.f, aw = 0.f, es = 0.f;
    int idx = (start < end) ? g_csrd[start] : 0;
    for (int i = start; i < end; i++) {
        int nidx = (i + 1 < end) ? g_csrd[i + 1] : 0;
        float4 hs = *(const float4*)(g_h + idx * DO + q * 4);
        ax += hs.x; ay += hs.y; az += hs.z; aw += hs.w;
        if (q == 0) es += g_nh[idx];
        idx = nidx;
    }
    *(float4*)(g_A + v * DO + q * 4) = make_float4(ax, ay, az, aw);
    float4 hv = *(const float4*)(g_h + v * DO + q * 4);
    float p = hv.x * ax + hv.y * ay + hv.z * az + hv.w * aw;
#pragma unroll
    for (int off = 8; off; off >>= 1)
        p += __shfl_down_sync(0xffffffffu, p, off, 16);
    if (q == 0)
        g_e[v] = (float)g_degd[v] * g_nh[v] - 2.f * p + es;
}

// ---------------- online softmax scalars --------------------------------------
__device__ __forceinline__ void triple_merge(float& m, float& z, float& t,
                                             float m2, float z2, float t2) {
    float M = fmaxf(m, m2);
    float a = expf(m - M), c = expf(m2 - M);
    z = z * a + z2 * c;
    t = t * a + t2 * c;
    m = M;
}

__global__ __launch_bounds__(256) void k_sum(const float* __restrict__ temp) {
    float tmp = temp[0];
    float m = -1e30f, z = 0.f, t = 0.f;
    for (int i = blockIdx.x * 256 + threadIdx.x; i < NN; i += NSUMB * 256) {
        float s = -g_e[i] / tmp;
        float M = fmaxf(m, s);
        float a = expf(m - M), c = expf(s - M);
        z = z * a + c;
        t = t * a + s * c;
        m = M;
    }
    __shared__ float sm[256], sz[256], st[256];
    sm[threadIdx.x] = m; sz[threadIdx.x] = z; st[threadIdx.x] = t;
    __syncthreads();
    for (int o = 128; o; o >>= 1) {
        if (threadIdx.x < o) {
            float mm = sm[threadIdx.x], zz = sz[threadIdx.x], tt = st[threadIdx.x];
            triple_merge(mm, zz, tt, sm[threadIdx.x + o], sz[threadIdx.x + o], st[threadIdx.x + o]);
            sm[threadIdx.x] = mm; sz[threadIdx.x] = zz; st[threadIdx.x] = tt;
        }
        __syncthreads();
    }
    if (threadIdx.x == 0) {
        g_pm[blockIdx.x] = sm[0]; g_pz[blockIdx.x] = sz[0]; g_pt[blockIdx.x] = st[0];
    }
}

__global__ __launch_bounds__(256) void k_q(const float* __restrict__ temp) {
    __shared__ float sm[256], sz[256], st[256];
    int tx = threadIdx.x;
    sm[tx] = g_pm[tx]; sz[tx] = g_pz[tx]; st[tx] = g_pt[tx];
    __syncthreads();
    for (int o = 128; o; o >>= 1) {
        if (tx < o) {
            float mm = sm[tx], zz = sz[tx], tt = st[tx];
            triple_merge(mm, zz, tt, sm[tx + o], sz[tx + o], st[tx + o]);
            sm[tx] = mm; sz[tx] = zz; st[tx] = tt;
        }
        __syncthreads();
    }
    float M = sm[0], Z = sz[0], T = st[0];
    float invZ = 1.f / Z;
    float L = M + logf(Z);
    float H = L - T * invZ;
    int v = blockIdx.x * 256 + tx;
    if (v >= NN) return;
    float tmp = temp[0];
    float s = -g_e[v] / tmp;
    g_q[v] = expf(s - M) * invZ * (s - L + H);
}

// pass3 + final (16 lanes per node, index prefetch)
__global__ __launch_bounds__(256) void k_pass3(const float* __restrict__ wgt,
                                               float* __restrict__ out) {
    int t = blockIdx.x * 256 + threadIdx.x;
    int v = t >> 4, q = t & 15;
    if (v >= NN) return;
    int start = g_offs[v], end = g_offs[v + 1];
    float bx = 0.f, by = 0.f, bz = 0.f, bw = 0.f, Qs = 0.f;
    int idx = (start < end) ? g_csrs[start] : 0;
    for (int i = start; i < end; i++) {
        int nidx = (i + 1 < end) ? g_csrs[i + 1] : 0;
        float qd = g_q[idx];
        float4 hd = *(const float4*)(g_h + idx * DO + q * 4);
        bx += qd * hd.x; by += qd * hd.y; bz += qd * hd.z; bw += qd * hd.w;
        Qs += qd;
        idx = nidx;
    }
    float4 hv = *(const float4*)(g_h + v * DO + q * 4);
    float4 Av = *(const float4*)(g_A + v * DO + q * 4);
    float qv = g_q[v];
    float dg = (float)g_degd[v];
    float w2 = 2.f * wgt[0];
    float4 o;
    o.x = hv.x + w2 * (qv * (dg * hv.x - Av.x) + Qs * hv.x - bx);
    o.y = hv.y + w2 * (qv * (dg * hv.y - Av.y) + Qs * hv.y - by);
    o.z = hv.z + w2 * (qv * (dg * hv.z - Av.z) + Qs * hv.z - bz);
    o.w = hv.w + w2 * (qv * (dg * hv.w - Av.w) + Qs * hv.w - bw);
    *(float4*)(out + v * DO + q * 4) = o;
}

// ---------------- launch ----------------------------------------------------
extern "C" void kernel_launch(void* const* d_in, const int* in_sizes, int n_in,
                              void* d_out, int out_size) {
    const float* x    = (const float*)d_in[0];
    const int*   ei   = (const int*)d_in[1];
    const float* wgt  = (const float*)d_in[2];
    const float* temp = (const float*)d_in[3];
    const float* W    = (const float*)d_in[4];
    const float* b    = (const float*)d_in[5];
    float* out = (float*)d_out;

    static cudaStream_t s2 = nullptr, s3 = nullptr;
    static cudaEvent_t evA = nullptr, evB = nullptr, evC = nullptr, evD = nullptr;
    if (s2 == nullptr) {
        cudaStreamCreateWithFlags(&s2, cudaStreamNonBlocking);
        cudaStreamCreateWithFlags(&s3, cudaStreamNonBlocking);
        cudaEventCreateWithFlags(&evA, cudaEventDisableTiming);
        cudaEventCreateWithFlags(&evB, cudaEventDisableTiming);
        cudaEventCreateWithFlags(&evC, cudaEventDisableTiming);
        cudaEventCreateWithFlags(&evD, cudaEventDisableTiming);
    }

    const int NB_E   = (NE + 255) / 256;
    const int NB_E2  = (NE / 2 + 255) / 256;
    const int NB_N   = (NN + 255) / 256;
    const int NB_N16 = (NN * 16 + 255) / 256;

    // fork: GEMM on side stream s2
    cudaEventRecord(evA, 0);
    cudaStreamWaitEvent(s2, evA, 0);
    k_gemm<<<(NN + 127) / 128, 128, 0, s2>>>(x, W);
    cudaEventRecord(evB, s2);

    // CSR build on main stream
    k_zero<<<NB_N, 256>>>();
    k_deg<<<NB_E2, 256>>>(ei);
    k_scan1<<<NBLK_SCAN, SB>>>();
    k_scan2<<<1, 128>>>();
    k_scan3<<<NB_N, 256>>>();
    cudaEventRecord(evD, 0);
    k_fill_d<<<NB_E, 256>>>(ei);

    // src-CSR fill on s3, overlapped with pass1/pass2
    cudaStreamWaitEvent(s3, evD, 0);
    k_fill_s<<<NB_E, 256, 0, s3>>>(ei);
    cudaEventRecord(evC, s3);

    // join GEMM
    cudaStreamWaitEvent(0, evB, 0);
    k_pass1<<<NB_N16, 256>>>(b);
    k_pass2<<<NB_N16, 256>>>();
    k_sum<<<NSUMB, 256>>>(temp);
    k_q<<<NB_N, 256>>>(temp);

    // join src-CSR
    cudaStreamWaitEvent(0, evC, 0);
    k_pass3<<<NB_N16, 256>>>(wgt, out);
}